// round 3
// baseline (speedup 1.0000x reference)
#include <cuda_runtime.h>

// Problem constants (fixed shapes from reference)
#define Bz 8
#define Tz 1024
#define Cz 1024
#define Hz 16
#define Dz 64
#define Mz (Bz*Tz)   // 8192

// Scratch (device globals; no allocation allowed)
__device__ float g_q[Bz*Hz*Tz*Dz];   // [b][h][t][d]
__device__ float g_k[Bz*Hz*Tz*Dz];
__device__ float g_v[Bz*Hz*Tz*Dz];
__device__ float g_y[Bz*Tz*Cz];      // attention output, [b][t][h*64+d]

// ---------------------------------------------------------------------------
// 128x128-tile SGEMM, K=1024 fixed. 256 threads, 8x8 per thread
// (2x2 quadrants of 4x4, quadrant stride 64 in both m and n).
// A: [M,1024] row-major (if A==nullptr, uses g_y)
// Bm: [1024,N] row-major
// scatter_qkv: 1 -> epilogue scatters into g_q/g_k/g_v head-major (+bias)
//              0 -> epilogue writes out[m*N+n] (+bias)
// ---------------------------------------------------------------------------
__global__ void __launch_bounds__(256) sgemm_kernel(
    const float* __restrict__ A,
    const float* __restrict__ Bm,
    const float* __restrict__ bias,
    float* __restrict__ out,
    int N, int scatter_qkv)
{
    __shared__ float As[8*128];   // As[k][m] (transposed)
    __shared__ float Bs[8*128];   // Bs[k][n]

    if (A == nullptr) A = g_y;

    const int tid = threadIdx.x;
    const int tx  = tid & 15;
    const int ty  = tid >> 4;
    const int n0  = blockIdx.x * 128;
    const int m0  = blockIdx.y * 128;

    float acc[8][8] = {};   // [ii<4: row ty*4+ii | ii>=4: row 64+ty*4+ii-4]
                            // [jj<4: col tx*4+jj | jj>=4: col 64+tx*4+jj-4]

    // Global-load indexing
    const int ar = tid >> 1;          // 0..127  (A row within tile)
    const int ak = (tid & 1) * 4;     // 0 or 4  (A k-subchunk)
    const int bk = tid >> 5;          // 0..7    (B k row)
    const int bn = (tid & 31) * 4;    // 0..124  (B col chunk)

    const float* Aptr = A  + (size_t)(m0 + ar) * 1024 + ak;
    const float* Bptr = Bm + (size_t)bk * N + n0 + bn;

    for (int k0 = 0; k0 < 1024; k0 += 8) {
        float4 a4 = *(const float4*)(Aptr + k0);
        float4 b4 = *(const float4*)(Bptr + (size_t)k0 * N);
        As[(ak+0)*128 + ar] = a4.x;
        As[(ak+1)*128 + ar] = a4.y;
        As[(ak+2)*128 + ar] = a4.z;
        As[(ak+3)*128 + ar] = a4.w;
        *(float4*)&Bs[bk*128 + bn] = b4;
        __syncthreads();

        #pragma unroll
        for (int k = 0; k < 8; k++) {
            float4 a0 = *(float4*)&As[k*128 + ty*4];
            float4 a1 = *(float4*)&As[k*128 + 64 + ty*4];
            float4 b0 = *(float4*)&Bs[k*128 + tx*4];
            float4 b1 = *(float4*)&Bs[k*128 + 64 + tx*4];
            float av[8] = {a0.x,a0.y,a0.z,a0.w, a1.x,a1.y,a1.z,a1.w};
            float bv[8] = {b0.x,b0.y,b0.z,b0.w, b1.x,b1.y,b1.z,b1.w};
            #pragma unroll
            for (int ii = 0; ii < 8; ii++)
                #pragma unroll
                for (int jj = 0; jj < 8; jj++)
                    acc[ii][jj] += av[ii] * bv[jj];
        }
        __syncthreads();
    }

    // Epilogue: two column groups (cg) x two row groups (rg)
    #pragma unroll
    for (int cg = 0; cg < 2; cg++) {
        const int nbase = n0 + cg*64 + tx*4;      // global col of 4-wide group
        float4 bv4 = *(const float4*)&bias[nbase];

        if (!scatter_qkv) {
            #pragma unroll
            for (int rg = 0; rg < 2; rg++)
                #pragma unroll
                for (int ii = 0; ii < 4; ii++) {
                    int m = m0 + rg*64 + ty*4 + ii;
                    float4 r = make_float4(acc[rg*4+ii][cg*4+0] + bv4.x,
                                           acc[rg*4+ii][cg*4+1] + bv4.y,
                                           acc[rg*4+ii][cg*4+2] + bv4.z,
                                           acc[rg*4+ii][cg*4+3] + bv4.w);
                    *(float4*)&out[(size_t)m * N + nbase] = r;
                }
        } else {
            // 64-col chunk => single (which, head); nbase&63 == tx*4
            int which = nbase >> 10;             // 0=q 1=k 2=v
            int h     = (nbase >> 6) & 15;
            float* dst = (which == 0) ? g_q : ((which == 1) ? g_k : g_v);
            #pragma unroll
            for (int rg = 0; rg < 2; rg++)
                #pragma unroll
                for (int ii = 0; ii < 4; ii++) {
                    int m = m0 + rg*64 + ty*4 + ii;
                    int b = m >> 10;
                    int t = m & 1023;
                    float4 r = make_float4(acc[rg*4+ii][cg*4+0] + bv4.x,
                                           acc[rg*4+ii][cg*4+1] + bv4.y,
                                           acc[rg*4+ii][cg*4+2] + bv4.z,
                                           acc[rg*4+ii][cg*4+3] + bv4.w);
                    *(float4*)&dst[((size_t)(b*Hz + h)*Tz + t)*Dz + tx*4] = r;
                }
        }
    }
}

// ---------------------------------------------------------------------------
// Flash attention (causal), per (query-block of 64, b*h).
// 256 threads as 16x16; each thread owns 4 rows x 4 cols.
// Smem: Qs[d][i] (d-major), KP = Ks[d][j] aliased with Ps[i][k], Vs[k][d].
// ---------------------------------------------------------------------------
__global__ void __launch_bounds__(256) attn_kernel()
{
    __shared__ float Qs[64*64];
    __shared__ float KP[64*64];
    __shared__ float Vs[64*64];

    const int tid = threadIdx.x;
    const int tx  = tid & 15;
    const int ty  = tid >> 4;
    const int qb  = blockIdx.x;
    const int bh  = blockIdx.y;
    const int q0  = qb * 64;

    // Load Q tile transposed: Qs[d][i]
    const float4* qg4 = (const float4*)(g_q + (size_t)bh*Tz*Dz + (size_t)q0*Dz);
    #pragma unroll
    for (int r = 0; r < 4; r++) {
        int idx4 = r*256 + tid;
        int i  = idx4 >> 4;     // row within 64
        int d4 = idx4 & 15;     // float4 index within row
        float4 v = qg4[idx4];
        Qs[(d4*4+0)*64 + i] = v.x;
        Qs[(d4*4+1)*64 + i] = v.y;
        Qs[(d4*4+2)*64 + i] = v.z;
        Qs[(d4*4+3)*64 + i] = v.w;
    }

    float mrow[4], lrow[4], O[4][4];
    #pragma unroll
    for (int ii = 0; ii < 4; ii++) {
        mrow[ii] = -1e30f;
        lrow[ii] = 0.f;
        #pragma unroll
        for (int jj = 0; jj < 4; jj++) O[ii][jj] = 0.f;
    }

    for (int kb = 0; kb <= qb; kb++) {
        __syncthreads();   // protect KP/Vs from previous iteration's readers

        const float4* kg4 = (const float4*)(g_k + (size_t)bh*Tz*Dz + (size_t)kb*64*Dz);
        const float4* vg4 = (const float4*)(g_v + (size_t)bh*Tz*Dz + (size_t)kb*64*Dz);
        #pragma unroll
        for (int r = 0; r < 4; r++) {
            int idx4 = r*256 + tid;
            int j  = idx4 >> 4;
            int d4 = idx4 & 15;
            float4 kv = kg4[idx4];
            KP[(d4*4+0)*64 + j] = kv.x;
            KP[(d4*4+1)*64 + j] = kv.y;
            KP[(d4*4+2)*64 + j] = kv.z;
            KP[(d4*4+3)*64 + j] = kv.w;
            ((float4*)Vs)[idx4] = vg4[idx4];
        }
        __syncthreads();

        // S = Q K^T  (4x4 per thread)
        float S[4][4] = {};
        #pragma unroll 16
        for (int d = 0; d < 64; d++) {
            float4 q  = *(float4*)&Qs[d*64 + ty*4];
            float4 kk = *(float4*)&KP[d*64 + tx*4];
            float qv[4] = {q.x, q.y, q.z, q.w};
            float kv[4] = {kk.x, kk.y, kk.z, kk.w};
            #pragma unroll
            for (int ii = 0; ii < 4; ii++)
                #pragma unroll
                for (int jj = 0; jj < 4; jj++)
                    S[ii][jj] += qv[ii] * kv[jj];
        }

        // scale + causal mask (diagonal block only)
        const float sc = 0.125f; // 1/sqrt(64)
        #pragma unroll
        for (int ii = 0; ii < 4; ii++)
            #pragma unroll
            for (int jj = 0; jj < 4; jj++) {
                S[ii][jj] *= sc;
                if (kb == qb && (tx*4 + jj) > (ty*4 + ii)) S[ii][jj] = -1e30f;
            }

        // online softmax: reduce over the 16-lane column group
        float P[4][4];
        #pragma unroll
        for (int ii = 0; ii < 4; ii++) {
            float pm = fmaxf(fmaxf(S[ii][0], S[ii][1]), fmaxf(S[ii][2], S[ii][3]));
            #pragma unroll
            for (int off = 8; off >= 1; off >>= 1)
                pm = fmaxf(pm, __shfl_xor_sync(0xffffffffu, pm, off));
            float mn    = fmaxf(mrow[ii], pm);
            float alpha = __expf(mrow[ii] - mn);
            float rs = 0.f;
            #pragma unroll
            for (int jj = 0; jj < 4; jj++) {
                P[ii][jj] = __expf(S[ii][jj] - mn);
                rs += P[ii][jj];
            }
            #pragma unroll
            for (int off = 8; off >= 1; off >>= 1)
                rs += __shfl_xor_sync(0xffffffffu, rs, off);
            lrow[ii] = lrow[ii] * alpha + rs;
            mrow[ii] = mn;
            #pragma unroll
            for (int jj = 0; jj < 4; jj++) O[ii][jj] *= alpha;
        }

        __syncthreads();   // all K reads done; safe to overwrite KP with P
        #pragma unroll
        for (int ii = 0; ii < 4; ii++)
            *(float4*)&KP[(ty*4+ii)*64 + tx*4] =
                make_float4(P[ii][0], P[ii][1], P[ii][2], P[ii][3]);
        __syncthreads();

        // O += P @ V
        #pragma unroll 8
        for (int k = 0; k < 64; k++) {
            float4 v4 = *(float4*)&Vs[k*64 + tx*4];
            #pragma unroll
            for (int ii = 0; ii < 4; ii++) {
                float p = KP[(ty*4+ii)*64 + k];
                O[ii][0] += p * v4.x;
                O[ii][1] += p * v4.y;
                O[ii][2] += p * v4.z;
                O[ii][3] += p * v4.w;
            }
        }
    }

    // normalize + write to g_y [b][t][h*64+d]
    const int b = bh >> 4;
    const int h = bh & 15;
    #pragma unroll
    for (int ii = 0; ii < 4; ii++) {
        float inv = 1.0f / lrow[ii];
        int t = q0 + ty*4 + ii;
        float4 r = make_float4(O[ii][0]*inv, O[ii][1]*inv, O[ii][2]*inv, O[ii][3]*inv);
        *(float4*)&g_y[((size_t)(b*Tz + t))*Cz + h*Dz + tx*4] = r;
    }
}

// ---------------------------------------------------------------------------
extern "C" void kernel_launch(void* const* d_in, const int* in_sizes, int n_in,
                              void* d_out, int out_size)
{
    const float* x     = (const float*)d_in[0];
    const float* Wqkv  = (const float*)d_in[1];
    const float* bqkv  = (const float*)d_in[2];
    const float* Wproj = (const float*)d_in[3];
    const float* bproj = (const float*)d_in[4];
    float* out = (float*)d_out;

    dim3 blk(256);
    // 1) QKV GEMM + bias, scatter into head-major g_q/g_k/g_v
    sgemm_kernel<<<dim3(3072/128, Mz/128), blk>>>(x, Wqkv, bqkv, nullptr, 3072, 1);
    // 2) causal flash attention -> g_y
    attn_kernel<<<dim3(Tz/64, Bz*Hz), blk>>>();
    // 3) output projection + bias -> d_out
    sgemm_kernel<<<dim3(Cz/128, Mz/128), blk>>>(nullptr, Wproj, bproj, out, 1024, 0);
}

// round 4
// speedup vs baseline: 1.1285x; 1.1285x over previous
#include <cuda_runtime.h>

// Problem constants (fixed shapes from reference)
#define Bz 8
#define Tz 1024
#define Cz 1024
#define Hz 16
#define Dz 64
#define Mz (Bz*Tz)   // 8192

typedef unsigned long long u64;

// ---- packed f32x2 helpers (sm_103a) ---------------------------------------
__device__ __forceinline__ u64 pack2(float x, float y) {
    u64 r; asm("mov.b64 %0, {%1, %2};" : "=l"(r) : "f"(x), "f"(y)); return r;
}
__device__ __forceinline__ float2 unpack2(u64 v) {
    float2 f; asm("mov.b64 {%0, %1}, %2;" : "=f"(f.x), "=f"(f.y) : "l"(v)); return f;
}
__device__ __forceinline__ u64 ffma2(u64 a, u64 b, u64 c) {
    u64 d; asm("fma.rn.f32x2 %0, %1, %2, %3;" : "=l"(d) : "l"(a), "l"(b), "l"(c)); return d;
}
__device__ __forceinline__ u64 fmul2(u64 a, u64 b) {
    u64 d; asm("mul.rn.f32x2 %0, %1, %2;" : "=l"(d) : "l"(a), "l"(b)); return d;
}

// Scratch (device globals; no allocation allowed)
__device__ float g_q[Bz*Hz*Tz*Dz];   // [b][h][t][d]
__device__ float g_k[Bz*Hz*Tz*Dz];
__device__ float g_v[Bz*Hz*Tz*Dz];
__device__ float g_y[Bz*Tz*Cz];      // attention output, [b][t][h*64+d]

// ---------------------------------------------------------------------------
// 128x128-tile SGEMM, K=1024 fixed. 256 threads, 8x8 per thread,
// accumulators held as f32x2 pairs; inner product via fma.rn.f32x2.
// ---------------------------------------------------------------------------
__global__ void __launch_bounds__(256) sgemm_kernel(
    const float* __restrict__ A,
    const float* __restrict__ Bm,
    const float* __restrict__ bias,
    float* __restrict__ out,
    int N, int scatter_qkv)
{
    __shared__ float As[8*128];   // As[k][m] (transposed)
    __shared__ float Bs[8*128];   // Bs[k][n]

    if (A == nullptr) A = g_y;

    const int tid = threadIdx.x;
    const int tx  = tid & 15;
    const int ty  = tid >> 4;
    const int n0  = blockIdx.x * 128;
    const int m0  = blockIdx.y * 128;

    // acc2[ii][j2]: row group ii (ii<4: ty*4+ii ; ii>=4: 64+ty*4+ii-4),
    // col pair j2 (j2<2: cols tx*4+2*j2.. ; j2>=2: cols 64+tx*4+2*(j2-2)..)
    u64 acc2[8][4];
    #pragma unroll
    for (int i = 0; i < 8; i++)
        #pragma unroll
        for (int j = 0; j < 4; j++) acc2[i][j] = 0ull;

    const int ar = tid >> 1;          // 0..127
    const int ak = (tid & 1) * 4;     // 0 or 4
    const int bk = tid >> 5;          // 0..7
    const int bn = (tid & 31) * 4;    // 0..124

    const float* Aptr = A  + (size_t)(m0 + ar) * 1024 + ak;
    const float* Bptr = Bm + (size_t)bk * N + n0 + bn;

    float4 a4 = *(const float4*)(Aptr);
    float4 b4 = *(const float4*)(Bptr);

    for (int k0 = 0; k0 < 1024; k0 += 8) {
        As[(ak+0)*128 + ar] = a4.x;
        As[(ak+1)*128 + ar] = a4.y;
        As[(ak+2)*128 + ar] = a4.z;
        As[(ak+3)*128 + ar] = a4.w;
        *(float4*)&Bs[bk*128 + bn] = b4;
        __syncthreads();

        if (k0 + 8 < 1024) {
            a4 = *(const float4*)(Aptr + k0 + 8);
            b4 = *(const float4*)(Bptr + (size_t)(k0 + 8) * N);
        }

        #pragma unroll
        for (int k = 0; k < 8; k++) {
            float4 a0 = *(float4*)&As[k*128 + ty*4];
            float4 a1 = *(float4*)&As[k*128 + 64 + ty*4];
            float4 b0 = *(float4*)&Bs[k*128 + tx*4];
            float4 b1 = *(float4*)&Bs[k*128 + 64 + tx*4];
            u64 b2[4] = { pack2(b0.x, b0.y), pack2(b0.z, b0.w),
                          pack2(b1.x, b1.y), pack2(b1.z, b1.w) };
            float av[8] = {a0.x,a0.y,a0.z,a0.w, a1.x,a1.y,a1.z,a1.w};
            #pragma unroll
            for (int ii = 0; ii < 8; ii++) {
                u64 ad = pack2(av[ii], av[ii]);
                #pragma unroll
                for (int j2 = 0; j2 < 4; j2++)
                    acc2[ii][j2] = ffma2(ad, b2[j2], acc2[ii][j2]);
            }
        }
        __syncthreads();
    }

    // Epilogue
    #pragma unroll
    for (int cg = 0; cg < 2; cg++) {
        const int nbase = n0 + cg*64 + tx*4;
        float4 bv4 = *(const float4*)&bias[nbase];

        if (!scatter_qkv) {
            #pragma unroll
            for (int rg = 0; rg < 2; rg++)
                #pragma unroll
                for (int ii = 0; ii < 4; ii++) {
                    float2 c0 = unpack2(acc2[rg*4+ii][cg*2+0]);
                    float2 c1 = unpack2(acc2[rg*4+ii][cg*2+1]);
                    int m = m0 + rg*64 + ty*4 + ii;
                    float4 r = make_float4(c0.x + bv4.x, c0.y + bv4.y,
                                           c1.x + bv4.z, c1.y + bv4.w);
                    *(float4*)&out[(size_t)m * N + nbase] = r;
                }
        } else {
            int which = nbase >> 10;             // 0=q 1=k 2=v
            int h     = (nbase >> 6) & 15;
            float* dst = (which == 0) ? g_q : ((which == 1) ? g_k : g_v);
            #pragma unroll
            for (int rg = 0; rg < 2; rg++)
                #pragma unroll
                for (int ii = 0; ii < 4; ii++) {
                    float2 c0 = unpack2(acc2[rg*4+ii][cg*2+0]);
                    float2 c1 = unpack2(acc2[rg*4+ii][cg*2+1]);
                    int m = m0 + rg*64 + ty*4 + ii;
                    int b = m >> 10;
                    int t = m & 1023;
                    float4 r = make_float4(c0.x + bv4.x, c0.y + bv4.y,
                                           c1.x + bv4.z, c1.y + bv4.w);
                    *(float4*)&dst[((size_t)(b*Hz + h)*Tz + t)*Dz + tx*4] = r;
                }
        }
    }
}

// ---------------------------------------------------------------------------
// Flash attention (causal), per (query-block of 64, b*h). 256 threads 16x16,
// 4x4 per thread; inner products via fma.rn.f32x2.
// ---------------------------------------------------------------------------
__global__ void __launch_bounds__(256) attn_kernel()
{
    __shared__ float Qs[64*64];
    __shared__ float KP[64*64];
    __shared__ float Vs[64*64];

    const int tid = threadIdx.x;
    const int tx  = tid & 15;
    const int ty  = tid >> 4;
    const int qb  = blockIdx.x;
    const int bh  = blockIdx.y;
    const int q0  = qb * 64;

    // Load Q tile transposed: Qs[d][i]
    const float4* qg4 = (const float4*)(g_q + (size_t)bh*Tz*Dz + (size_t)q0*Dz);
    #pragma unroll
    for (int r = 0; r < 4; r++) {
        int idx4 = r*256 + tid;
        int i  = idx4 >> 4;
        int d4 = idx4 & 15;
        float4 v = qg4[idx4];
        Qs[(d4*4+0)*64 + i] = v.x;
        Qs[(d4*4+1)*64 + i] = v.y;
        Qs[(d4*4+2)*64 + i] = v.z;
        Qs[(d4*4+3)*64 + i] = v.w;
    }

    float mrow[4], lrow[4];
    u64 O2[4][2];
    #pragma unroll
    for (int ii = 0; ii < 4; ii++) {
        mrow[ii] = -1e30f;
        lrow[ii] = 0.f;
        O2[ii][0] = 0ull; O2[ii][1] = 0ull;
    }

    for (int kb = 0; kb <= qb; kb++) {
        __syncthreads();   // protect KP/Vs from previous iteration's readers

        const float4* kg4 = (const float4*)(g_k + (size_t)bh*Tz*Dz + (size_t)kb*64*Dz);
        const float4* vg4 = (const float4*)(g_v + (size_t)bh*Tz*Dz + (size_t)kb*64*Dz);
        #pragma unroll
        for (int r = 0; r < 4; r++) {
            int idx4 = r*256 + tid;
            int j  = idx4 >> 4;
            int d4 = idx4 & 15;
            float4 kv = kg4[idx4];
            KP[(d4*4+0)*64 + j] = kv.x;
            KP[(d4*4+1)*64 + j] = kv.y;
            KP[(d4*4+2)*64 + j] = kv.z;
            KP[(d4*4+3)*64 + j] = kv.w;
            ((float4*)Vs)[idx4] = vg4[idx4];
        }
        __syncthreads();

        // S = Q K^T  (4x4 per thread, f32x2 packed along columns)
        u64 S2[4][2] = {};
        #pragma unroll 16
        for (int d = 0; d < 64; d++) {
            float4 q  = *(float4*)&Qs[d*64 + ty*4];
            float4 kk = *(float4*)&KP[d*64 + tx*4];
            u64 k2[2] = { pack2(kk.x, kk.y), pack2(kk.z, kk.w) };
            float qv[4] = {q.x, q.y, q.z, q.w};
            #pragma unroll
            for (int ii = 0; ii < 4; ii++) {
                u64 qd = pack2(qv[ii], qv[ii]);
                S2[ii][0] = ffma2(qd, k2[0], S2[ii][0]);
                S2[ii][1] = ffma2(qd, k2[1], S2[ii][1]);
            }
        }

        float S[4][4];
        #pragma unroll
        for (int ii = 0; ii < 4; ii++) {
            float2 s0 = unpack2(S2[ii][0]);
            float2 s1 = unpack2(S2[ii][1]);
            S[ii][0] = s0.x; S[ii][1] = s0.y; S[ii][2] = s1.x; S[ii][3] = s1.y;
        }

        // scale + causal mask (diagonal block only)
        const float sc = 0.125f; // 1/sqrt(64)
        #pragma unroll
        for (int ii = 0; ii < 4; ii++)
            #pragma unroll
            for (int jj = 0; jj < 4; jj++) {
                S[ii][jj] *= sc;
                if (kb == qb && (tx*4 + jj) > (ty*4 + ii)) S[ii][jj] = -1e30f;
            }

        // online softmax: reduce over the 16-lane column group
        float P[4][4];
        #pragma unroll
        for (int ii = 0; ii < 4; ii++) {
            float pm = fmaxf(fmaxf(S[ii][0], S[ii][1]), fmaxf(S[ii][2], S[ii][3]));
            #pragma unroll
            for (int off = 8; off >= 1; off >>= 1)
                pm = fmaxf(pm, __shfl_xor_sync(0xffffffffu, pm, off));
            float mn    = fmaxf(mrow[ii], pm);
            float alpha = __expf(mrow[ii] - mn);
            float rs = 0.f;
            #pragma unroll
            for (int jj = 0; jj < 4; jj++) {
                P[ii][jj] = __expf(S[ii][jj] - mn);
                rs += P[ii][jj];
            }
            #pragma unroll
            for (int off = 8; off >= 1; off >>= 1)
                rs += __shfl_xor_sync(0xffffffffu, rs, off);
            lrow[ii] = lrow[ii] * alpha + rs;
            mrow[ii] = mn;
            u64 a2 = pack2(alpha, alpha);
            O2[ii][0] = fmul2(O2[ii][0], a2);
            O2[ii][1] = fmul2(O2[ii][1], a2);
        }

        __syncthreads();   // all K reads done; safe to overwrite KP with P
        #pragma unroll
        for (int ii = 0; ii < 4; ii++)
            *(float4*)&KP[(ty*4+ii)*64 + tx*4] =
                make_float4(P[ii][0], P[ii][1], P[ii][2], P[ii][3]);
        __syncthreads();

        // O += P @ V  (f32x2 packed along d)
        #pragma unroll 8
        for (int k = 0; k < 64; k++) {
            float4 v4 = *(float4*)&Vs[k*64 + tx*4];
            u64 v2[2] = { pack2(v4.x, v4.y), pack2(v4.z, v4.w) };
            #pragma unroll
            for (int ii = 0; ii < 4; ii++) {
                float p = KP[(ty*4+ii)*64 + k];
                u64 pd = pack2(p, p);
                O2[ii][0] = ffma2(pd, v2[0], O2[ii][0]);
                O2[ii][1] = ffma2(pd, v2[1], O2[ii][1]);
            }
        }
    }

    // normalize + write to g_y [b][t][h*64+d]
    const int b = bh >> 4;
    const int h = bh & 15;
    #pragma unroll
    for (int ii = 0; ii < 4; ii++) {
        float inv = 1.0f / lrow[ii];
        int t = q0 + ty*4 + ii;
        float2 o0 = unpack2(O2[ii][0]);
        float2 o1 = unpack2(O2[ii][1]);
        float4 r = make_float4(o0.x*inv, o0.y*inv, o1.x*inv, o1.y*inv);
        *(float4*)&g_y[((size_t)(b*Tz + t))*Cz + h*Dz + tx*4] = r;
    }
}

// ---------------------------------------------------------------------------
extern "C" void kernel_launch(void* const* d_in, const int* in_sizes, int n_in,
                              void* d_out, int out_size)
{
    const float* x     = (const float*)d_in[0];
    const float* Wqkv  = (const float*)d_in[1];
    const float* bqkv  = (const float*)d_in[2];
    const float* Wproj = (const float*)d_in[3];
    const float* bproj = (const float*)d_in[4];
    float* out = (float*)d_out;

    dim3 blk(256);
    // 1) QKV GEMM + bias, scatter into head-major g_q/g_k/g_v
    sgemm_kernel<<<dim3(3072/128, Mz/128), blk>>>(x, Wqkv, bqkv, nullptr, 3072, 1);
    // 2) causal flash attention -> g_y
    attn_kernel<<<dim3(Tz/64, Bz*Hz), blk>>>();
    // 3) output projection + bias -> d_out
    sgemm_kernel<<<dim3(Cz/128, Mz/128), blk>>>(nullptr, Wproj, bproj, out, 1024, 0);
}

// round 7
// speedup vs baseline: 1.6221x; 1.4374x over previous
#include <cuda_runtime.h>
#include <cuda_bf16.h>
#include <cstdint>

// Problem constants (fixed shapes from reference)
#define Bz 8
#define Tz 1024
#define Cz 1024
#define Hz 16
#define Dz 64
#define Mz (Bz*Tz)   // 8192

typedef unsigned long long u64;

// ---- packed f32x2 helpers (sm_103a; pairwise fp32 ops) ---------------------
__device__ __forceinline__ u64 pack2(float x, float y) {
    u64 r; asm("mov.b64 %0, {%1, %2};" : "=l"(r) : "f"(x), "f"(y)); return r;
}
__device__ __forceinline__ float2 unpack2(u64 v) {
    float2 f; asm("mov.b64 {%0, %1}, %2;" : "=f"(f.x), "=f"(f.y) : "l"(v)); return f;
}
__device__ __forceinline__ u64 ffma2(u64 a, u64 b, u64 c) {
    u64 d; asm("fma.rn.f32x2 %0, %1, %2, %3;" : "=l"(d) : "l"(a), "l"(b), "l"(c)); return d;
}
__device__ __forceinline__ u64 fmul2(u64 a, u64 b) {
    u64 d; asm("mul.rn.f32x2 %0, %1, %2;" : "=l"(d) : "l"(a), "l"(b)); return d;
}

// ---- mma / ldmatrix helpers (arch-agnostic PTX, legal on compute_103) ------
__device__ __forceinline__ uint32_t smem_to_u32(const void* p) {
    uint32_t a;
    asm("{ .reg .u64 t; cvta.to.shared.u64 t, %1; cvt.u32.u64 %0, t; }" : "=r"(a) : "l"(p));
    return a;
}
__device__ __forceinline__ void ldm4(uint32_t* r, uint32_t addr) {
    asm volatile("ldmatrix.sync.aligned.m8n8.x4.shared.b16 {%0,%1,%2,%3}, [%4];"
                 : "=r"(r[0]), "=r"(r[1]), "=r"(r[2]), "=r"(r[3]) : "r"(addr));
}
__device__ __forceinline__ void mma_bf16(float* c, const uint32_t* a, const uint32_t* b) {
    asm volatile("mma.sync.aligned.m16n8k16.row.col.f32.bf16.bf16.f32 "
                 "{%0,%1,%2,%3},{%4,%5,%6,%7},{%8,%9},{%0,%1,%2,%3};"
                 : "+f"(c[0]), "+f"(c[1]), "+f"(c[2]), "+f"(c[3])
                 : "r"(a[0]), "r"(a[1]), "r"(a[2]), "r"(a[3]), "r"(b[0]), "r"(b[1]));
}

// ---- scratch (device globals; no allocation allowed) -----------------------
__device__ float g_q[Bz*Hz*Tz*Dz];   // [b][h][t][d]
__device__ float g_k[Bz*Hz*Tz*Dz];
__device__ float g_v[Bz*Hz*Tz*Dz];
__device__ float g_y[Bz*Tz*Cz];      // attention output, [b][t][h*64+d]

__device__ __nv_bfloat16 g_xhi[Mz*Cz];       // x split, [M][1024]
__device__ __nv_bfloat16 g_xlo[Mz*Cz];
__device__ __nv_bfloat16 g_yhi[Mz*Cz];       // y split
__device__ __nv_bfloat16 g_ylo[Mz*Cz];
__device__ __nv_bfloat16 g_wqkv_hi[3*Cz*Cz]; // Wqkv^T [3072][1024]
__device__ __nv_bfloat16 g_wqkv_lo[3*Cz*Cz];
__device__ __nv_bfloat16 g_wprj_hi[Cz*Cz];   // Wproj^T [1024][1024]
__device__ __nv_bfloat16 g_wprj_lo[Cz*Cz];

// ---------------------------------------------------------------------------
// Prep: fp32 -> bf16 hi/lo (x from input, y from g_y)
// ---------------------------------------------------------------------------
__device__ __forceinline__ void split4(const float* f, uint2& h4, uint2& l4) {
    uint32_t h2[2], l2[2];
    #pragma unroll
    for (int p = 0; p < 2; p++) {
        __nv_bfloat16 h0 = __float2bfloat16(f[2*p+0]);
        __nv_bfloat16 h1 = __float2bfloat16(f[2*p+1]);
        __nv_bfloat16 l0 = __float2bfloat16(f[2*p+0] - __bfloat162float(h0));
        __nv_bfloat16 l1 = __float2bfloat16(f[2*p+1] - __bfloat162float(h1));
        h2[p] = (uint32_t)__bfloat16_as_ushort(h0) | ((uint32_t)__bfloat16_as_ushort(h1) << 16);
        l2[p] = (uint32_t)__bfloat16_as_ushort(l0) | ((uint32_t)__bfloat16_as_ushort(l1) << 16);
    }
    h4 = make_uint2(h2[0], h2[1]);
    l4 = make_uint2(l2[0], l2[1]);
}

__global__ void __launch_bounds__(256) cvt_x_kernel(const float* __restrict__ in)
{
    const int n4 = Mz*Cz/4;
    for (int i = blockIdx.x * blockDim.x + threadIdx.x; i < n4; i += gridDim.x * blockDim.x) {
        float4 v = ((const float4*)in)[i];
        float f[4] = {v.x, v.y, v.z, v.w};
        uint2 h4, l4; split4(f, h4, l4);
        ((uint2*)g_xhi)[i] = h4;
        ((uint2*)g_xlo)[i] = l4;
    }
}

__global__ void __launch_bounds__(256) cvt_y_kernel()
{
    const int n4 = Mz*Cz/4;
    for (int i = blockIdx.x * blockDim.x + threadIdx.x; i < n4; i += gridDim.x * blockDim.x) {
        float4 v = ((const float4*)g_y)[i];
        float f[4] = {v.x, v.y, v.z, v.w};
        uint2 h4, l4; split4(f, h4, l4);
        ((uint2*)g_yhi)[i] = h4;
        ((uint2*)g_ylo)[i] = l4;
    }
}

// ---------------------------------------------------------------------------
// Prep: W [1024 k][N n] fp32 -> Wt [N][1024] bf16 hi/lo (transpose + split)
// which: 0 -> g_wqkv_*, 1 -> g_wprj_*
// ---------------------------------------------------------------------------
__global__ void __launch_bounds__(256) transpose_cvt_kernel(
    const float* __restrict__ W, int N, int which)
{
    __shared__ float t[32][33];
    __nv_bfloat16* Thi = which ? g_wprj_hi : g_wqkv_hi;
    __nv_bfloat16* Tlo = which ? g_wprj_lo : g_wqkv_lo;
    const int n0 = blockIdx.x * 32, k0 = blockIdx.y * 32;
    const int tx = threadIdx.x, ty = threadIdx.y;   // (32, 8)
    #pragma unroll
    for (int j = ty; j < 32; j += 8)
        t[j][tx] = W[(size_t)(k0 + j) * N + n0 + tx];
    __syncthreads();
    #pragma unroll
    for (int j = ty; j < 32; j += 8) {
        float f = t[tx][j];                          // = W[k0+tx][n0+j]
        __nv_bfloat16 h = __float2bfloat16(f);
        __nv_bfloat16 l = __float2bfloat16(f - __bfloat162float(h));
        size_t o = (size_t)(n0 + j) * 1024 + k0 + tx;
        Thi[o] = h; Tlo[o] = l;
    }
}

// ---------------------------------------------------------------------------
// bf16 3-split GEMM via mma.sync (HMMA):  D = Ah*Bh + Ah*Bl + Al*Bh
// out[M,N] = A[M,1024] x Bt[N,1024]^T + bias
// 128x128 CTA tile, BK=16, double-buffered 48KB static smem,
// 8 warps as 2(m) x 4(n), warp tile 64x32, m16n8k16 atoms.
// mode: 0 -> A=g_x*, B=g_wqkv*, scatter epilogue into g_q/g_k/g_v
//       1 -> A=g_y*, B=g_wprj*, write out[m*N+n]
// smem rows padded to 48B (bank(r)=12r mod 32: conflict-free for ldmatrix).
// ---------------------------------------------------------------------------
#define TILE_B  6144          // 128 rows * 48B
#define BUF_B   (4*TILE_B)    // Ah, Al, Bh, Bl

__global__ void __launch_bounds__(256, 2) mma_gemm_kernel(
    int mode, int N, const float* __restrict__ bias, float* __restrict__ out)
{
    __shared__ __align__(16) char smem[2*BUF_B];   // 49152 B exactly

    const int tid  = threadIdx.x;
    const int lane = tid & 31;
    const int wid  = tid >> 5;
    const int warp_m = wid & 1;        // 0..1 (64 rows each)
    const int warp_n = wid >> 1;       // 0..3 (32 cols each)
    const int m0 = blockIdx.y * 128;
    const int n0 = blockIdx.x * 128;

    const __nv_bfloat16 *Ahp, *Alp, *Bhp, *Blp;
    if (mode == 0) { Ahp = g_xhi; Alp = g_xlo; Bhp = g_wqkv_hi; Blp = g_wqkv_lo; }
    else           { Ahp = g_yhi; Alp = g_ylo; Bhp = g_wprj_hi; Blp = g_wprj_lo; }

    // global load indexing: thread t loads one uint4 (16B = 8 bf16) per tile
    const int gr   = tid >> 1;          // row 0..127 within tile
    const int gh   = tid & 1;           // 16B half within the 32B (k16) row chunk
    const uint4* pAh = (const uint4*)Ahp + (size_t)(m0 + gr) * 128 + gh;
    const uint4* pAl = (const uint4*)Alp + (size_t)(m0 + gr) * 128 + gh;
    const uint4* pBh = (const uint4*)Bhp + (size_t)(n0 + gr) * 128 + gh;
    const uint4* pBl = (const uint4*)Blp + (size_t)(n0 + gr) * 128 + gh;
    const int st_off = gr * 48 + gh * 16;

    // ldmatrix per-lane addresses (within a tile)
    const uint32_t sbase = smem_to_u32(smem);
    const int midx = lane >> 3;         // which 8x8 matrix this lane addresses
    // A atoms: m0=rows0-7 k0-7, m1=rows8-15 k0-7, m2=rows0-7 k8-15, m3=rows8-15 k8-15
    const int rowA = warp_m*64 + (lane & 7) + 8*(midx & 1);
    const int colA = (midx >> 1) * 16;  // bytes: 0 or 16 (k0-7 / k8-15)
    // B atoms: m0=n0-7 k0-7, m1=n0-7 k8-15, m2=n8-15 k0-7, m3=n8-15 k8-15
    const int rowB = warp_n*32 + (lane & 7) + 8*(midx >> 1);
    const int colB = (midx & 1) * 16;

    float acc[4][4][4];
    #pragma unroll
    for (int i = 0; i < 4; i++)
        #pragma unroll
        for (int j = 0; j < 4; j++)
            #pragma unroll
            for (int r = 0; r < 4; r++) acc[i][j][r] = 0.f;

    uint4 pf0 = pAh[0], pf1 = pAl[0], pf2 = pBh[0], pf3 = pBl[0];

    for (int kc = 0; kc < 64; kc++) {
        const int bufo = (kc & 1) * BUF_B;
        char* s = smem + bufo;
        *(uint4*)(s + 0*TILE_B + st_off) = pf0;
        *(uint4*)(s + 1*TILE_B + st_off) = pf1;
        *(uint4*)(s + 2*TILE_B + st_off) = pf2;
        *(uint4*)(s + 3*TILE_B + st_off) = pf3;
        __syncthreads();

        if (kc < 63) {
            const int g = (kc + 1) * 2;
            pf0 = pAh[g]; pf1 = pAl[g]; pf2 = pBh[g]; pf3 = pBl[g];
        }

        // B fragments (hi & lo): 2 ldmatrix.x4 each cover 2 n8 atoms
        uint32_t bh[2][4], bl[2][4];
        #pragma unroll
        for (int p = 0; p < 2; p++) {
            uint32_t ab = sbase + bufo + (uint32_t)((rowB + p*16) * 48 + colB);
            ldm4(bh[p], ab + 2*TILE_B);
            ldm4(bl[p], ab + 3*TILE_B);
        }

        #pragma unroll
        for (int mi = 0; mi < 4; mi++) {
            uint32_t ah[4], al[4];
            uint32_t aa = sbase + bufo + (uint32_t)((rowA + mi*16) * 48 + colA);
            ldm4(ah, aa);
            ldm4(al, aa + TILE_B);
            #pragma unroll
            for (int ni = 0; ni < 4; ni++)
                mma_bf16(acc[mi][ni], ah, &bh[ni >> 1][2*(ni & 1)]);
            #pragma unroll
            for (int ni = 0; ni < 4; ni++)
                mma_bf16(acc[mi][ni], ah, &bl[ni >> 1][2*(ni & 1)]);
            #pragma unroll
            for (int ni = 0; ni < 4; ni++)
                mma_bf16(acc[mi][ni], al, &bh[ni >> 1][2*(ni & 1)]);
        }
        __syncthreads();
    }

    // Epilogue: bias + store (float2 per atom row), direct from registers.
    const int g4 = lane >> 2;      // row within atom (0..7)
    const int c2 = 2 * (lane & 3); // col pair within atom
    #pragma unroll
    for (int mi = 0; mi < 4; mi++) {
        #pragma unroll
        for (int ni = 0; ni < 4; ni++) {
            int m = m0 + warp_m*64 + mi*16 + g4;
            int n = n0 + warp_n*32 + ni*8 + c2;
            float2 bv = *(const float2*)&bias[n];
            float2 v0 = make_float2(acc[mi][ni][0] + bv.x, acc[mi][ni][1] + bv.y);
            float2 v1 = make_float2(acc[mi][ni][2] + bv.x, acc[mi][ni][3] + bv.y);
            if (mode == 1) {
                *(float2*)&out[(size_t)m * N + n]       = v0;
                *(float2*)&out[(size_t)(m+8) * N + n]   = v1;
            } else {
                int which = n >> 10;            // 0=q 1=k 2=v
                int h = (n >> 6) & 15;
                int d = n & 63;
                float* dst = (which == 0) ? g_q : ((which == 1) ? g_k : g_v);
                int b0i = m >> 10,  t0 = m & 1023;
                int b1i = (m+8) >> 10, t1 = (m+8) & 1023;
                *(float2*)&dst[((size_t)(b0i*Hz + h)*Tz + t0)*Dz + d] = v0;
                *(float2*)&dst[((size_t)(b1i*Hz + h)*Tz + t1)*Dz + d] = v1;
            }
        }
    }
}

// ---------------------------------------------------------------------------
// Flash attention (causal), unchanged from R4 (passing, fp32 + f32x2).
// ---------------------------------------------------------------------------
__global__ void __launch_bounds__(256) attn_kernel()
{
    __shared__ float Qs[64*64];
    __shared__ float KP[64*64];
    __shared__ float Vs[64*64];

    const int tid = threadIdx.x;
    const int tx  = tid & 15;
    const int ty  = tid >> 4;
    const int qb  = blockIdx.x;
    const int bh  = blockIdx.y;
    const int q0  = qb * 64;

    const float4* qg4 = (const float4*)(g_q + (size_t)bh*Tz*Dz + (size_t)q0*Dz);
    #pragma unroll
    for (int r = 0; r < 4; r++) {
        int idx4 = r*256 + tid;
        int i  = idx4 >> 4;
        int d4 = idx4 & 15;
        float4 v = qg4[idx4];
        Qs[(d4*4+0)*64 + i] = v.x;
        Qs[(d4*4+1)*64 + i] = v.y;
        Qs[(d4*4+2)*64 + i] = v.z;
        Qs[(d4*4+3)*64 + i] = v.w;
    }

    float mrow[4], lrow[4];
    u64 O2[4][2];
    #pragma unroll
    for (int ii = 0; ii < 4; ii++) {
        mrow[ii] = -1e30f;
        lrow[ii] = 0.f;
        O2[ii][0] = 0ull; O2[ii][1] = 0ull;
    }

    for (int kb = 0; kb <= qb; kb++) {
        __syncthreads();

        const float4* kg4 = (const float4*)(g_k + (size_t)bh*Tz*Dz + (size_t)kb*64*Dz);
        const float4* vg4 = (const float4*)(g_v + (size_t)bh*Tz*Dz + (size_t)kb*64*Dz);
        #pragma unroll
        for (int r = 0; r < 4; r++) {
            int idx4 = r*256 + tid;
            int j  = idx4 >> 4;
            int d4 = idx4 & 15;
            float4 kv = kg4[idx4];
            KP[(d4*4+0)*64 + j] = kv.x;
            KP[(d4*4+1)*64 + j] = kv.y;
            KP[(d4*4+2)*64 + j] = kv.z;
            KP[(d4*4+3)*64 + j] = kv.w;
            ((float4*)Vs)[idx4] = vg4[idx4];
        }
        __syncthreads();

        u64 S2[4][2] = {};
        #pragma unroll 16
        for (int d = 0; d < 64; d++) {
            float4 q  = *(float4*)&Qs[d*64 + ty*4];
            float4 kk = *(float4*)&KP[d*64 + tx*4];
            u64 k2[2] = { pack2(kk.x, kk.y), pack2(kk.z, kk.w) };
            float qv[4] = {q.x, q.y, q.z, q.w};
            #pragma unroll
            for (int ii = 0; ii < 4; ii++) {
                u64 qd = pack2(qv[ii], qv[ii]);
                S2[ii][0] = ffma2(qd, k2[0], S2[ii][0]);
                S2[ii][1] = ffma2(qd, k2[1], S2[ii][1]);
            }
        }

        float S[4][4];
        #pragma unroll
        for (int ii = 0; ii < 4; ii++) {
            float2 s0 = unpack2(S2[ii][0]);
            float2 s1 = unpack2(S2[ii][1]);
            S[ii][0] = s0.x; S[ii][1] = s0.y; S[ii][2] = s1.x; S[ii][3] = s1.y;
        }

        const float sc = 0.125f;
        #pragma unroll
        for (int ii = 0; ii < 4; ii++)
            #pragma unroll
            for (int jj = 0; jj < 4; jj++) {
                S[ii][jj] *= sc;
                if (kb == qb && (tx*4 + jj) > (ty*4 + ii)) S[ii][jj] = -1e30f;
            }

        float P[4][4];
        #pragma unroll
        for (int ii = 0; ii < 4; ii++) {
            float pm = fmaxf(fmaxf(S[ii][0], S[ii][1]), fmaxf(S[ii][2], S[ii][3]));
            #pragma unroll
            for (int off = 8; off >= 1; off >>= 1)
                pm = fmaxf(pm, __shfl_xor_sync(0xffffffffu, pm, off));
            float mn    = fmaxf(mrow[ii], pm);
            float alpha = __expf(mrow[ii] - mn);
            float rs = 0.f;
            #pragma unroll
            for (int jj = 0; jj < 4; jj++) {
                P[ii][jj] = __expf(S[ii][jj] - mn);
                rs += P[ii][jj];
            }
            #pragma unroll
            for (int off = 8; off >= 1; off >>= 1)
                rs += __shfl_xor_sync(0xffffffffu, rs, off);
            lrow[ii] = lrow[ii] * alpha + rs;
            mrow[ii] = mn;
            u64 a2 = pack2(alpha, alpha);
            O2[ii][0] = fmul2(O2[ii][0], a2);
            O2[ii][1] = fmul2(O2[ii][1], a2);
        }

        __syncthreads();
        #pragma unroll
        for (int ii = 0; ii < 4; ii++)
            *(float4*)&KP[(ty*4+ii)*64 + tx*4] =
                make_float4(P[ii][0], P[ii][1], P[ii][2], P[ii][3]);
        __syncthreads();

        #pragma unroll 8
        for (int k = 0; k < 64; k++) {
            float4 v4 = *(float4*)&Vs[k*64 + tx*4];
            u64 v2[2] = { pack2(v4.x, v4.y), pack2(v4.z, v4.w) };
            #pragma unroll
            for (int ii = 0; ii < 4; ii++) {
                float p = KP[(ty*4+ii)*64 + k];
                u64 pd = pack2(p, p);
                O2[ii][0] = ffma2(pd, v2[0], O2[ii][0]);
                O2[ii][1] = ffma2(pd, v2[1], O2[ii][1]);
            }
        }
    }

    const int b = bh >> 4;
    const int h = bh & 15;
    #pragma unroll
    for (int ii = 0; ii < 4; ii++) {
        float inv = 1.0f / lrow[ii];
        int t = q0 + ty*4 + ii;
        float2 o0 = unpack2(O2[ii][0]);
        float2 o1 = unpack2(O2[ii][1]);
        float4 r = make_float4(o0.x*inv, o0.y*inv, o1.x*inv, o1.y*inv);
        *(float4*)&g_y[((size_t)(b*Tz + t))*Cz + h*Dz + tx*4] = r;
    }
}

// ---------------------------------------------------------------------------
extern "C" void kernel_launch(void* const* d_in, const int* in_sizes, int n_in,
                              void* d_out, int out_size)
{
    const float* x     = (const float*)d_in[0];
    const float* Wqkv  = (const float*)d_in[1];
    const float* bqkv  = (const float*)d_in[2];
    const float* Wproj = (const float*)d_in[3];
    const float* bproj = (const float*)d_in[4];
    float* out = (float*)d_out;

    // 1) prep: x -> bf16 hi/lo ; W^T -> bf16 hi/lo
    cvt_x_kernel<<<2048, 256>>>(x);
    transpose_cvt_kernel<<<dim3(3*Cz/32, Cz/32), dim3(32,8)>>>(Wqkv, 3*Cz, 0);
    transpose_cvt_kernel<<<dim3(Cz/32,   Cz/32), dim3(32,8)>>>(Wproj, Cz, 1);

    // 2) QKV GEMM (HMMA, 3-split) -> scatter into g_q/g_k/g_v
    mma_gemm_kernel<<<dim3(3*Cz/128, Mz/128), 256>>>(0, 3*Cz, bqkv, nullptr);

    // 3) causal flash attention -> g_y
    attn_kernel<<<dim3(Tz/64, Bz*Hz), 256>>>();

    // 4) y -> bf16 hi/lo, proj GEMM (HMMA, 3-split) -> d_out
    cvt_y_kernel<<<2048, 256>>>();
    mma_gemm_kernel<<<dim3(Cz/128, Mz/128), 256>>>(1, Cz, bproj, out);
}

// round 8
// speedup vs baseline: 2.5373x; 1.5642x over previous
#include <cuda_runtime.h>
#include <cuda_bf16.h>
#include <cuda_fp16.h>
#include <cstdint>

// Problem constants (fixed shapes from reference)
#define Bz 8
#define Tz 1024
#define Cz 1024
#define Hz 16
#define Dz 64
#define Mz (Bz*Tz)   // 8192

typedef unsigned long long u64;

// ---- mma / ldmatrix helpers (arch-agnostic PTX, legal on compute_103) ------
__device__ __forceinline__ uint32_t smem_to_u32(const void* p) {
    uint32_t a;
    asm("{ .reg .u64 t; cvta.to.shared.u64 t, %1; cvt.u32.u64 %0, t; }" : "=r"(a) : "l"(p));
    return a;
}
__device__ __forceinline__ void ldm4(uint32_t* r, uint32_t addr) {
    asm volatile("ldmatrix.sync.aligned.m8n8.x4.shared.b16 {%0,%1,%2,%3}, [%4];"
                 : "=r"(r[0]), "=r"(r[1]), "=r"(r[2]), "=r"(r[3]) : "r"(addr));
}
__device__ __forceinline__ void ldm4t(uint32_t* r, uint32_t addr) {
    asm volatile("ldmatrix.sync.aligned.m8n8.x4.trans.shared.b16 {%0,%1,%2,%3}, [%4];"
                 : "=r"(r[0]), "=r"(r[1]), "=r"(r[2]), "=r"(r[3]) : "r"(addr));
}
__device__ __forceinline__ void mma_bf16(float* c, const uint32_t* a, const uint32_t* b) {
    asm volatile("mma.sync.aligned.m16n8k16.row.col.f32.bf16.bf16.f32 "
                 "{%0,%1,%2,%3},{%4,%5,%6,%7},{%8,%9},{%0,%1,%2,%3};"
                 : "+f"(c[0]), "+f"(c[1]), "+f"(c[2]), "+f"(c[3])
                 : "r"(a[0]), "r"(a[1]), "r"(a[2]), "r"(a[3]), "r"(b[0]), "r"(b[1]));
}
__device__ __forceinline__ void mma_f16(float* c, const uint32_t* a, const uint32_t* b) {
    asm volatile("mma.sync.aligned.m16n8k16.row.col.f32.f16.f16.f32 "
                 "{%0,%1,%2,%3},{%4,%5,%6,%7},{%8,%9},{%0,%1,%2,%3};"
                 : "+f"(c[0]), "+f"(c[1]), "+f"(c[2]), "+f"(c[3])
                 : "r"(a[0]), "r"(a[1]), "r"(a[2]), "r"(a[3]), "r"(b[0]), "r"(b[1]));
}

// ---- scratch (device globals; no allocation allowed) -----------------------
__device__ float g_q[Bz*Hz*Tz*Dz];   // [b][h][t][d]
__device__ float g_k[Bz*Hz*Tz*Dz];
__device__ float g_v[Bz*Hz*Tz*Dz];
__device__ float g_y[Bz*Tz*Cz];      // attention output, [b][t][h*64+d]

__device__ __nv_bfloat16 g_xhi[Mz*Cz];       // x split, [M][1024]
__device__ __nv_bfloat16 g_xlo[Mz*Cz];
__device__ __nv_bfloat16 g_yhi[Mz*Cz];       // y split
__device__ __nv_bfloat16 g_ylo[Mz*Cz];
__device__ __nv_bfloat16 g_wqkv_hi[3*Cz*Cz]; // Wqkv^T [3072][1024]
__device__ __nv_bfloat16 g_wqkv_lo[3*Cz*Cz];
__device__ __nv_bfloat16 g_wprj_hi[Cz*Cz];   // Wproj^T [1024][1024]
__device__ __nv_bfloat16 g_wprj_lo[Cz*Cz];

// ---------------------------------------------------------------------------
// Prep: fp32 -> bf16 hi/lo (x from input, y from g_y)
// ---------------------------------------------------------------------------
__device__ __forceinline__ void split4(const float* f, uint2& h4, uint2& l4) {
    uint32_t h2[2], l2[2];
    #pragma unroll
    for (int p = 0; p < 2; p++) {
        __nv_bfloat16 h0 = __float2bfloat16(f[2*p+0]);
        __nv_bfloat16 h1 = __float2bfloat16(f[2*p+1]);
        __nv_bfloat16 l0 = __float2bfloat16(f[2*p+0] - __bfloat162float(h0));
        __nv_bfloat16 l1 = __float2bfloat16(f[2*p+1] - __bfloat162float(h1));
        h2[p] = (uint32_t)__bfloat16_as_ushort(h0) | ((uint32_t)__bfloat16_as_ushort(h1) << 16);
        l2[p] = (uint32_t)__bfloat16_as_ushort(l0) | ((uint32_t)__bfloat16_as_ushort(l1) << 16);
    }
    h4 = make_uint2(h2[0], h2[1]);
    l4 = make_uint2(l2[0], l2[1]);
}

__global__ void __launch_bounds__(256) cvt_x_kernel(const float* __restrict__ in)
{
    const int n4 = Mz*Cz/4;
    for (int i = blockIdx.x * blockDim.x + threadIdx.x; i < n4; i += gridDim.x * blockDim.x) {
        float4 v = ((const float4*)in)[i];
        float f[4] = {v.x, v.y, v.z, v.w};
        uint2 h4, l4; split4(f, h4, l4);
        ((uint2*)g_xhi)[i] = h4;
        ((uint2*)g_xlo)[i] = l4;
    }
}

__global__ void __launch_bounds__(256) cvt_y_kernel()
{
    const int n4 = Mz*Cz/4;
    for (int i = blockIdx.x * blockDim.x + threadIdx.x; i < n4; i += gridDim.x * blockDim.x) {
        float4 v = ((const float4*)g_y)[i];
        float f[4] = {v.x, v.y, v.z, v.w};
        uint2 h4, l4; split4(f, h4, l4);
        ((uint2*)g_yhi)[i] = h4;
        ((uint2*)g_ylo)[i] = l4;
    }
}

// ---------------------------------------------------------------------------
// Prep: W [1024 k][N n] fp32 -> Wt [N][1024] bf16 hi/lo (transpose + split)
// ---------------------------------------------------------------------------
__global__ void __launch_bounds__(256) transpose_cvt_kernel(
    const float* __restrict__ W, int N, int which)
{
    __shared__ float t[32][33];
    __nv_bfloat16* Thi = which ? g_wprj_hi : g_wqkv_hi;
    __nv_bfloat16* Tlo = which ? g_wprj_lo : g_wqkv_lo;
    const int n0 = blockIdx.x * 32, k0 = blockIdx.y * 32;
    const int tx = threadIdx.x, ty = threadIdx.y;   // (32, 8)
    #pragma unroll
    for (int j = ty; j < 32; j += 8)
        t[j][tx] = W[(size_t)(k0 + j) * N + n0 + tx];
    __syncthreads();
    #pragma unroll
    for (int j = ty; j < 32; j += 8) {
        float f = t[tx][j];                          // = W[k0+tx][n0+j]
        __nv_bfloat16 h = __float2bfloat16(f);
        __nv_bfloat16 l = __float2bfloat16(f - __bfloat162float(h));
        size_t o = (size_t)(n0 + j) * 1024 + k0 + tx;
        Thi[o] = h; Tlo[o] = l;
    }
}

// ---------------------------------------------------------------------------
// bf16 3-split GEMM via mma.sync (HMMA) — unchanged from R7 (passing).
// ---------------------------------------------------------------------------
#define TILE_B  6144          // 128 rows * 48B
#define BUF_B   (4*TILE_B)    // Ah, Al, Bh, Bl

__global__ void __launch_bounds__(256, 2) mma_gemm_kernel(
    int mode, int N, const float* __restrict__ bias, float* __restrict__ out)
{
    __shared__ __align__(16) char smem[2*BUF_B];   // 49152 B exactly

    const int tid  = threadIdx.x;
    const int lane = tid & 31;
    const int wid  = tid >> 5;
    const int warp_m = wid & 1;
    const int warp_n = wid >> 1;
    const int m0 = blockIdx.y * 128;
    const int n0 = blockIdx.x * 128;

    const __nv_bfloat16 *Ahp, *Alp, *Bhp, *Blp;
    if (mode == 0) { Ahp = g_xhi; Alp = g_xlo; Bhp = g_wqkv_hi; Blp = g_wqkv_lo; }
    else           { Ahp = g_yhi; Alp = g_ylo; Bhp = g_wprj_hi; Blp = g_wprj_lo; }

    const int gr   = tid >> 1;
    const int gh   = tid & 1;
    const uint4* pAh = (const uint4*)Ahp + (size_t)(m0 + gr) * 128 + gh;
    const uint4* pAl = (const uint4*)Alp + (size_t)(m0 + gr) * 128 + gh;
    const uint4* pBh = (const uint4*)Bhp + (size_t)(n0 + gr) * 128 + gh;
    const uint4* pBl = (const uint4*)Blp + (size_t)(n0 + gr) * 128 + gh;
    const int st_off = gr * 48 + gh * 16;

    const uint32_t sbase = smem_to_u32(smem);
    const int midx = lane >> 3;
    const int rowA = warp_m*64 + (lane & 7) + 8*(midx & 1);
    const int colA = (midx >> 1) * 16;
    const int rowB = warp_n*32 + (lane & 7) + 8*(midx >> 1);
    const int colB = (midx & 1) * 16;

    float acc[4][4][4];
    #pragma unroll
    for (int i = 0; i < 4; i++)
        #pragma unroll
        for (int j = 0; j < 4; j++)
            #pragma unroll
            for (int r = 0; r < 4; r++) acc[i][j][r] = 0.f;

    uint4 pf0 = pAh[0], pf1 = pAl[0], pf2 = pBh[0], pf3 = pBl[0];

    for (int kc = 0; kc < 64; kc++) {
        const int bufo = (kc & 1) * BUF_B;
        char* s = smem + bufo;
        *(uint4*)(s + 0*TILE_B + st_off) = pf0;
        *(uint4*)(s + 1*TILE_B + st_off) = pf1;
        *(uint4*)(s + 2*TILE_B + st_off) = pf2;
        *(uint4*)(s + 3*TILE_B + st_off) = pf3;
        __syncthreads();

        if (kc < 63) {
            const int g = (kc + 1) * 2;
            pf0 = pAh[g]; pf1 = pAl[g]; pf2 = pBh[g]; pf3 = pBl[g];
        }

        uint32_t bh[2][4], bl[2][4];
        #pragma unroll
        for (int p = 0; p < 2; p++) {
            uint32_t ab = sbase + bufo + (uint32_t)((rowB + p*16) * 48 + colB);
            ldm4(bh[p], ab + 2*TILE_B);
            ldm4(bl[p], ab + 3*TILE_B);
        }

        #pragma unroll
        for (int mi = 0; mi < 4; mi++) {
            uint32_t ah[4], al[4];
            uint32_t aa = sbase + bufo + (uint32_t)((rowA + mi*16) * 48 + colA);
            ldm4(ah, aa);
            ldm4(al, aa + TILE_B);
            #pragma unroll
            for (int ni = 0; ni < 4; ni++)
                mma_bf16(acc[mi][ni], ah, &bh[ni >> 1][2*(ni & 1)]);
            #pragma unroll
            for (int ni = 0; ni < 4; ni++)
                mma_bf16(acc[mi][ni], ah, &bl[ni >> 1][2*(ni & 1)]);
            #pragma unroll
            for (int ni = 0; ni < 4; ni++)
                mma_bf16(acc[mi][ni], al, &bh[ni >> 1][2*(ni & 1)]);
        }
        __syncthreads();
    }

    const int g4 = lane >> 2;
    const int c2 = 2 * (lane & 3);
    #pragma unroll
    for (int mi = 0; mi < 4; mi++) {
        #pragma unroll
        for (int ni = 0; ni < 4; ni++) {
            int m = m0 + warp_m*64 + mi*16 + g4;
            int n = n0 + warp_n*32 + ni*8 + c2;
            float2 bv = *(const float2*)&bias[n];
            float2 v0 = make_float2(acc[mi][ni][0] + bv.x, acc[mi][ni][1] + bv.y);
            float2 v1 = make_float2(acc[mi][ni][2] + bv.x, acc[mi][ni][3] + bv.y);
            if (mode == 1) {
                *(float2*)&out[(size_t)m * N + n]       = v0;
                *(float2*)&out[(size_t)(m+8) * N + n]   = v1;
            } else {
                int which = n >> 10;
                int h = (n >> 6) & 15;
                int d = n & 63;
                float* dst = (which == 0) ? g_q : ((which == 1) ? g_k : g_v);
                int b0i = m >> 10,  t0 = m & 1023;
                int b1i = (m+8) >> 10, t1 = (m+8) & 1023;
                *(float2*)&dst[((size_t)(b0i*Hz + h)*Tz + t0)*Dz + d] = v0;
                *(float2*)&dst[((size_t)(b1i*Hz + h)*Tz + t1)*Dz + d] = v1;
            }
        }
    }
}

// ---------------------------------------------------------------------------
// Flash attention v2 (causal) on tensor cores.
// CTA: 64 q-rows x (b*h); 128 threads = 4 warps, warp w owns rows 16w..16w+15.
// S = Q K^T via bf16 3-split mma (Qh.Kh + Qh.Kl + Ql.Kh), softmax in regs,
// O += P V via single-pass fp16 mma (P accum layout == fp16 A-frag layout).
// Smem: tile stride 72 halves (144B) -> conflict-free ldmatrix.
// Q tiles aliased by K tiles (Q frags hoisted to registers first).
// ---------------------------------------------------------------------------
#define ASTRIDE 72

__global__ void __launch_bounds__(128) attn_kernel()
{
    __shared__ __align__(16) __nv_bfloat16 sT0[64*ASTRIDE];  // Qh, then Kh
    __shared__ __align__(16) __nv_bfloat16 sT1[64*ASTRIDE];  // Ql, then Kl
    __shared__ __align__(16) __half        sV [64*ASTRIDE];

    const int tid  = threadIdx.x;
    const int lane = tid & 31;
    const int w    = tid >> 5;         // 0..3
    const int qb   = blockIdx.x;
    const int bh   = blockIdx.y;
    const int q0   = qb * 64;

    const uint32_t a0 = smem_to_u32(sT0);
    const uint32_t a1 = smem_to_u32(sT1);
    const uint32_t av = smem_to_u32(sV);

    // ---- load Q tile -> bf16 hi/lo in smem ----
    {
        const float4* qg = (const float4*)(g_q + ((size_t)bh*Tz + q0)*Dz);
        #pragma unroll
        for (int u = 0; u < 8; u++) {
            int idx4 = tid + 128*u;
            int r = idx4 >> 4, d4 = idx4 & 15;
            float4 v = qg[idx4];
            __nv_bfloat16 h0 = __float2bfloat16(v.x), h1 = __float2bfloat16(v.y);
            __nv_bfloat16 h2 = __float2bfloat16(v.z), h3 = __float2bfloat16(v.w);
            __nv_bfloat16 l0 = __float2bfloat16(v.x - __bfloat162float(h0));
            __nv_bfloat16 l1 = __float2bfloat16(v.y - __bfloat162float(h1));
            __nv_bfloat16 l2 = __float2bfloat16(v.z - __bfloat162float(h2));
            __nv_bfloat16 l3 = __float2bfloat16(v.w - __bfloat162float(h3));
            __nv_bfloat162* ph = (__nv_bfloat162*)&sT0[r*ASTRIDE + d4*4];
            __nv_bfloat162* pl = (__nv_bfloat162*)&sT1[r*ASTRIDE + d4*4];
            ph[0] = __halves2bfloat162(h0, h1); ph[1] = __halves2bfloat162(h2, h3);
            pl[0] = __halves2bfloat162(l0, l1); pl[1] = __halves2bfloat162(l2, l3);
        }
    }
    __syncthreads();

    // ---- hoist Q A-frags (2 splits x 4 k-steps x 4 regs) ----
    uint32_t qh[4][4], ql[4][4];
    {
        const int rowA = 16*w + (lane & 7) + 8*((lane >> 3) & 1);
        const int colb = ((lane >> 4) & 1) * 16;
        #pragma unroll
        for (int j = 0; j < 4; j++) {
            uint32_t ad = (uint32_t)(rowA*144 + j*32 + colb);
            ldm4(qh[j], a0 + ad);
            ldm4(ql[j], a1 + ad);
        }
    }
    __syncthreads();   // Q smem now dead; K may overwrite

    float mr[2] = {-1e30f, -1e30f};
    float lr[2] = {0.f, 0.f};
    float O[8][4];
    #pragma unroll
    for (int aI = 0; aI < 8; aI++)
        #pragma unroll
        for (int e = 0; e < 4; e++) O[aI][e] = 0.f;

    const int r0loc = 16*w + (lane >> 2);   // block-local row for softmax/mask

    for (int kb = 0; kb <= qb; kb++) {
        // ---- load K (bf16 hi/lo) and V (fp16) tiles ----
        {
            const float4* kg = (const float4*)(g_k + ((size_t)bh*Tz + kb*64)*Dz);
            const float4* vg = (const float4*)(g_v + ((size_t)bh*Tz + kb*64)*Dz);
            #pragma unroll
            for (int u = 0; u < 8; u++) {
                int idx4 = tid + 128*u;
                int r = idx4 >> 4, d4 = idx4 & 15;
                float4 v = kg[idx4];
                __nv_bfloat16 h0 = __float2bfloat16(v.x), h1 = __float2bfloat16(v.y);
                __nv_bfloat16 h2 = __float2bfloat16(v.z), h3 = __float2bfloat16(v.w);
                __nv_bfloat16 l0 = __float2bfloat16(v.x - __bfloat162float(h0));
                __nv_bfloat16 l1 = __float2bfloat16(v.y - __bfloat162float(h1));
                __nv_bfloat16 l2 = __float2bfloat16(v.z - __bfloat162float(h2));
                __nv_bfloat16 l3 = __float2bfloat16(v.w - __bfloat162float(h3));
                __nv_bfloat162* ph = (__nv_bfloat162*)&sT0[r*ASTRIDE + d4*4];
                __nv_bfloat162* pl = (__nv_bfloat162*)&sT1[r*ASTRIDE + d4*4];
                ph[0] = __halves2bfloat162(h0, h1); ph[1] = __halves2bfloat162(h2, h3);
                pl[0] = __halves2bfloat162(l0, l1); pl[1] = __halves2bfloat162(l2, l3);
                float4 vv = vg[idx4];
                __half2* pv = (__half2*)&sV[r*ASTRIDE + d4*4];
                pv[0] = __floats2half2_rn(vv.x, vv.y);
                pv[1] = __floats2half2_rn(vv.z, vv.w);
            }
        }
        __syncthreads();

        // ---- S = Q K^T (3-split bf16) ----
        float S[8][4];
        #pragma unroll
        for (int aI = 0; aI < 8; aI++)
            #pragma unroll
            for (int e = 0; e < 4; e++) S[aI][e] = 0.f;

        const int rowB = (lane & 7) + 8*((lane >> 4) & 1);
        const int colbB = ((lane >> 3) & 1) * 16;
        #pragma unroll
        for (int j = 0; j < 4; j++) {
            #pragma unroll
            for (int p = 0; p < 4; p++) {
                uint32_t ad = (uint32_t)((16*p + rowB)*144 + j*32 + colbB);
                uint32_t kh4[4], kl4[4];
                ldm4(kh4, a0 + ad);
                ldm4(kl4, a1 + ad);
                mma_bf16(S[2*p],   qh[j], kh4);
                mma_bf16(S[2*p+1], qh[j], kh4 + 2);
                mma_bf16(S[2*p],   qh[j], kl4);
                mma_bf16(S[2*p+1], qh[j], kl4 + 2);
                mma_bf16(S[2*p],   ql[j], kh4);
                mma_bf16(S[2*p+1], ql[j], kh4 + 2);
            }
        }

        // ---- scale + causal mask (diagonal block only) ----
        const float sc = 0.125f;
        #pragma unroll
        for (int aI = 0; aI < 8; aI++) {
            int colb0 = 16*(aI >> 1) + 8*(aI & 1) + 2*(lane & 3);
            #pragma unroll
            for (int e = 0; e < 2; e++) {
                S[aI][e]   *= sc;
                S[aI][2+e] *= sc;
                if (kb == qb) {
                    if (colb0 + e > r0loc)     S[aI][e]   = -1e30f;
                    if (colb0 + e > r0loc + 8) S[aI][2+e] = -1e30f;
                }
            }
        }

        // ---- online softmax (rows r0loc and r0loc+8) ----
        float alpha[2];
        #pragma unroll
        for (int hrow = 0; hrow < 2; hrow++) {
            float mx = -1e30f;
            #pragma unroll
            for (int aI = 0; aI < 8; aI++)
                mx = fmaxf(mx, fmaxf(S[aI][2*hrow], S[aI][2*hrow+1]));
            mx = fmaxf(mx, __shfl_xor_sync(0xffffffffu, mx, 1));
            mx = fmaxf(mx, __shfl_xor_sync(0xffffffffu, mx, 2));
            float mn = fmaxf(mr[hrow], mx);
            alpha[hrow] = __expf(mr[hrow] - mn);
            mr[hrow] = mn;
            float rs = 0.f;
            #pragma unroll
            for (int aI = 0; aI < 8; aI++) {
                S[aI][2*hrow]   = __expf(S[aI][2*hrow]   - mn);
                S[aI][2*hrow+1] = __expf(S[aI][2*hrow+1] - mn);
                rs += S[aI][2*hrow] + S[aI][2*hrow+1];
            }
            rs += __shfl_xor_sync(0xffffffffu, rs, 1);
            rs += __shfl_xor_sync(0xffffffffu, rs, 2);
            lr[hrow] = lr[hrow] * alpha[hrow] + rs;
        }
        #pragma unroll
        for (int aI = 0; aI < 8; aI++) {
            O[aI][0] *= alpha[0]; O[aI][1] *= alpha[0];
            O[aI][2] *= alpha[1]; O[aI][3] *= alpha[1];
        }

        // ---- O += P V (fp16, P packed from S accums) ----
        #pragma unroll
        for (int j = 0; j < 4; j++) {
            uint32_t pa[4];
            __half2 t0 = __floats2half2_rn(S[2*j][0],   S[2*j][1]);
            __half2 t1 = __floats2half2_rn(S[2*j][2],   S[2*j][3]);
            __half2 t2 = __floats2half2_rn(S[2*j+1][0], S[2*j+1][1]);
            __half2 t3 = __floats2half2_rn(S[2*j+1][2], S[2*j+1][3]);
            pa[0] = *(uint32_t*)&t0; pa[1] = *(uint32_t*)&t1;
            pa[2] = *(uint32_t*)&t2; pa[3] = *(uint32_t*)&t3;
            const int rowV = 16*j + (lane & 7) + 8*((lane >> 3) & 1);
            #pragma unroll
            for (int q = 0; q < 4; q++) {
                uint32_t vb[4];
                ldm4t(vb, av + (uint32_t)(rowV*144 + (2*q + ((lane >> 4) & 1))*16));
                mma_f16(O[2*q],   pa, vb);
                mma_f16(O[2*q+1], pa, vb + 2);
            }
        }
        __syncthreads();   // protect K/V tiles before next iteration's overwrite
    }

    // ---- normalize + store to g_y [b][t][h*64+d] ----
    const float inv0 = 1.0f / lr[0];
    const float inv1 = 1.0f / lr[1];
    const int b = bh >> 4;
    const int h = bh & 15;
    const int t0g = q0 + r0loc;
    #pragma unroll
    for (int aI = 0; aI < 8; aI++) {
        int d = 16*(aI >> 1) + 8*(aI & 1) + 2*(lane & 3);
        *(float2*)&g_y[((size_t)(b*Tz + t0g))*Cz + h*Dz + d] =
            make_float2(O[aI][0]*inv0, O[aI][1]*inv0);
        *(float2*)&g_y[((size_t)(b*Tz + t0g + 8))*Cz + h*Dz + d] =
            make_float2(O[aI][2]*inv1, O[aI][3]*inv1);
    }
}

// ---------------------------------------------------------------------------
extern "C" void kernel_launch(void* const* d_in, const int* in_sizes, int n_in,
                              void* d_out, int out_size)
{
    const float* x     = (const float*)d_in[0];
    const float* Wqkv  = (const float*)d_in[1];
    const float* bqkv  = (const float*)d_in[2];
    const float* Wproj = (const float*)d_in[3];
    const float* bproj = (const float*)d_in[4];
    float* out = (float*)d_out;

    // 1) prep: x -> bf16 hi/lo ; W^T -> bf16 hi/lo
    cvt_x_kernel<<<2048, 256>>>(x);
    transpose_cvt_kernel<<<dim3(3*Cz/32, Cz/32), dim3(32,8)>>>(Wqkv, 3*Cz, 0);
    transpose_cvt_kernel<<<dim3(Cz/32,   Cz/32), dim3(32,8)>>>(Wproj, Cz, 1);

    // 2) QKV GEMM (HMMA, 3-split) -> scatter into g_q/g_k/g_v
    mma_gemm_kernel<<<dim3(3*Cz/128, Mz/128), 256>>>(0, 3*Cz, bqkv, nullptr);

    // 3) causal flash attention (HMMA) -> g_y
    attn_kernel<<<dim3(Tz/64, Bz*Hz), 128>>>();

    // 4) y -> bf16 hi/lo, proj GEMM (HMMA, 3-split) -> d_out
    cvt_y_kernel<<<2048, 256>>>();
    mma_gemm_kernel<<<dim3(Cz/128, Mz/128), 256>>>(1, Cz, bproj, out);
}

// round 9
// speedup vs baseline: 5.0076x; 1.9736x over previous
#include <cuda_runtime.h>
#include <cuda_fp16.h>
#include <cstdint>

// Problem constants (fixed shapes from reference)
#define Bz 8
#define Tz 1024
#define Cz 1024
#define Hz 16
#define Dz 64
#define Mz (Bz*Tz)   // 8192

// ---- mma / ldmatrix helpers (arch-agnostic PTX, legal on compute_103) ------
__device__ __forceinline__ uint32_t smem_to_u32(const void* p) {
    uint32_t a;
    asm("{ .reg .u64 t; cvta.to.shared.u64 t, %1; cvt.u32.u64 %0, t; }" : "=r"(a) : "l"(p));
    return a;
}
__device__ __forceinline__ void ldm4(uint32_t* r, uint32_t addr) {
    asm volatile("ldmatrix.sync.aligned.m8n8.x4.shared.b16 {%0,%1,%2,%3}, [%4];"
                 : "=r"(r[0]), "=r"(r[1]), "=r"(r[2]), "=r"(r[3]) : "r"(addr));
}
__device__ __forceinline__ void ldm4t(uint32_t* r, uint32_t addr) {
    asm volatile("ldmatrix.sync.aligned.m8n8.x4.trans.shared.b16 {%0,%1,%2,%3}, [%4];"
                 : "=r"(r[0]), "=r"(r[1]), "=r"(r[2]), "=r"(r[3]) : "r"(addr));
}
__device__ __forceinline__ void mma_f16(float* c, const uint32_t* a, const uint32_t* b) {
    asm volatile("mma.sync.aligned.m16n8k16.row.col.f32.f16.f16.f32 "
                 "{%0,%1,%2,%3},{%4,%5,%6,%7},{%8,%9},{%0,%1,%2,%3};"
                 : "+f"(c[0]), "+f"(c[1]), "+f"(c[2]), "+f"(c[3])
                 : "r"(a[0]), "r"(a[1]), "r"(a[2]), "r"(a[3]), "r"(b[0]), "r"(b[1]));
}

// ---- scratch (device globals; no allocation allowed) -----------------------
__device__ __align__(16) __half g_qh[Bz*Hz*Tz*Dz];   // [b][h][t][d] fp16
__device__ __align__(16) __half g_kh[Bz*Hz*Tz*Dz];
__device__ __align__(16) __half g_vh[Bz*Hz*Tz*Dz];
__device__ __align__(16) __half g_yh[Mz*Cz];         // attn out fp16, [m][h*64+d]
__device__ __align__(16) __half g_xh[Mz*Cz];         // x fp16, [M][1024]
__device__ __align__(16) __half g_wqkvh[3*Cz*Cz];    // Wqkv^T fp16 [3072][1024]
__device__ __align__(16) __half g_wprjh[Cz*Cz];      // Wproj^T fp16 [1024][1024]

// ---------------------------------------------------------------------------
// Prep: x fp32 -> fp16
// ---------------------------------------------------------------------------
__global__ void __launch_bounds__(256) cvt_x_kernel(const float* __restrict__ in)
{
    const int n4 = Mz*Cz/4;
    for (int i = blockIdx.x * blockDim.x + threadIdx.x; i < n4; i += gridDim.x * blockDim.x) {
        float4 v = ((const float4*)in)[i];
        __half2 h0 = __floats2half2_rn(v.x, v.y);
        __half2 h1 = __floats2half2_rn(v.z, v.w);
        ((uint2*)g_xh)[i] = make_uint2(*(uint32_t*)&h0, *(uint32_t*)&h1);
    }
}

// ---------------------------------------------------------------------------
// Prep: W [1024 k][N n] fp32 -> Wt [N][1024] fp16 (transpose + convert)
// which: 0 -> g_wqkvh, 1 -> g_wprjh
// ---------------------------------------------------------------------------
__global__ void __launch_bounds__(256) transpose_cvt_kernel(
    const float* __restrict__ W, int N, int which)
{
    __shared__ float t[32][33];
    __half* T = which ? g_wprjh : g_wqkvh;
    const int n0 = blockIdx.x * 32, k0 = blockIdx.y * 32;
    const int tx = threadIdx.x, ty = threadIdx.y;   // (32, 8)
    #pragma unroll
    for (int j = ty; j < 32; j += 8)
        t[j][tx] = W[(size_t)(k0 + j) * N + n0 + tx];
    __syncthreads();
    #pragma unroll
    for (int j = ty; j < 32; j += 8)
        T[(size_t)(n0 + j) * 1024 + k0 + tx] = __float2half(t[tx][j]);
}

// ---------------------------------------------------------------------------
// Single-pass fp16 GEMM via mma.sync:  out[M,N] = A[M,1024] x Bt[N,1024]^T + bias
// 128x128 CTA tile, BK=16, double-buffered smem (rows padded to 48B),
// 8 warps as 2(m) x 4(n), warp tile 64x32, m16n8k16 atoms.
// mode: 0 -> A=g_xh, B=g_wqkvh, scatter fp16 into g_qh/g_kh/g_vh
//       1 -> A=g_yh, B=g_wprjh, write fp32 out[m*N+n]
// ---------------------------------------------------------------------------
#define TILE_B  6144          // 128 rows * 48B (32B data + 16B pad)
#define BUF_B   (2*TILE_B)    // A, B

__global__ void __launch_bounds__(256, 2) mma_gemm_kernel(
    int mode, int N, const float* __restrict__ bias, float* __restrict__ out)
{
    __shared__ __align__(16) char smem[2*BUF_B];   // 24576 B

    const int tid  = threadIdx.x;
    const int lane = tid & 31;
    const int wid  = tid >> 5;
    const int warp_m = wid & 1;
    const int warp_n = wid >> 1;
    const int m0 = blockIdx.y * 128;
    const int n0 = blockIdx.x * 128;

    const __half* Ap = mode ? g_yh : g_xh;
    const __half* Bp = mode ? g_wprjh : g_wqkvh;

    const int gr   = tid >> 1;          // row 0..127 within tile
    const int gh   = tid & 1;           // 16B half of the 32B k16 row chunk
    const uint4* pA = (const uint4*)Ap + (size_t)(m0 + gr) * 128 + gh;
    const uint4* pB = (const uint4*)Bp + (size_t)(n0 + gr) * 128 + gh;
    const int st_off = gr * 48 + gh * 16;

    const uint32_t sbase = smem_to_u32(smem);
    const int midx = lane >> 3;
    const int rowA = warp_m*64 + (lane & 7) + 8*(midx & 1);
    const int colA = (midx >> 1) * 16;
    const int rowB = warp_n*32 + (lane & 7) + 8*(midx >> 1);
    const int colB = (midx & 1) * 16;

    float acc[4][4][4];
    #pragma unroll
    for (int i = 0; i < 4; i++)
        #pragma unroll
        for (int j = 0; j < 4; j++)
            #pragma unroll
            for (int r = 0; r < 4; r++) acc[i][j][r] = 0.f;

    uint4 pf0 = pA[0], pf1 = pB[0];

    for (int kc = 0; kc < 64; kc++) {
        const int bufo = (kc & 1) * BUF_B;
        char* s = smem + bufo;
        *(uint4*)(s + 0*TILE_B + st_off) = pf0;
        *(uint4*)(s + 1*TILE_B + st_off) = pf1;
        __syncthreads();

        if (kc < 63) {
            const int g = (kc + 1) * 2;
            pf0 = pA[g]; pf1 = pB[g];
        }

        uint32_t bf[2][4];
        #pragma unroll
        for (int p = 0; p < 2; p++)
            ldm4(bf[p], sbase + bufo + 1*TILE_B + (uint32_t)((rowB + p*16) * 48 + colB));

        #pragma unroll
        for (int mi = 0; mi < 4; mi++) {
            uint32_t af[4];
            ldm4(af, sbase + bufo + (uint32_t)((rowA + mi*16) * 48 + colA));
            #pragma unroll
            for (int ni = 0; ni < 4; ni++)
                mma_f16(acc[mi][ni], af, &bf[ni >> 1][2*(ni & 1)]);
        }
        __syncthreads();
    }

    // Epilogue: bias + store
    const int g4 = lane >> 2;
    const int c2 = 2 * (lane & 3);
    #pragma unroll
    for (int mi = 0; mi < 4; mi++) {
        #pragma unroll
        for (int ni = 0; ni < 4; ni++) {
            int m = m0 + warp_m*64 + mi*16 + g4;
            int n = n0 + warp_n*32 + ni*8 + c2;
            float2 bv = *(const float2*)&bias[n];
            float2 v0 = make_float2(acc[mi][ni][0] + bv.x, acc[mi][ni][1] + bv.y);
            float2 v1 = make_float2(acc[mi][ni][2] + bv.x, acc[mi][ni][3] + bv.y);
            if (mode == 1) {
                *(float2*)&out[(size_t)m * N + n]     = v0;
                *(float2*)&out[(size_t)(m+8) * N + n] = v1;
            } else {
                int which = n >> 10;            // 0=q 1=k 2=v
                int h = (n >> 6) & 15;
                int d = n & 63;
                __half* dst = (which == 0) ? g_qh : ((which == 1) ? g_kh : g_vh);
                int b0i = m >> 10,  t0 = m & 1023;
                int b1i = (m+8) >> 10, t1 = (m+8) & 1023;
                __half2 h0 = __floats2half2_rn(v0.x, v0.y);
                __half2 h1 = __floats2half2_rn(v1.x, v1.y);
                *(__half2*)&dst[((size_t)(b0i*Hz + h)*Tz + t0)*Dz + d] = h0;
                *(__half2*)&dst[((size_t)(b1i*Hz + h)*Tz + t1)*Dz + d] = h1;
            }
        }
    }
}

// ---------------------------------------------------------------------------
// Flash attention v2 (causal), all-fp16 tensor-core path.
// CTA: 64 q-rows x (b*h); 128 threads = 4 warps, warp w owns rows 16w..16w+15.
// S = Q K^T single fp16 mma pass; softmax in regs; O += P V (fp16).
// Smem rows padded: ASTRIDE=72 halves (144B) -> conflict-free ldmatrix.
// Q tile aliased by K tile (Q frags hoisted to registers first).
// ---------------------------------------------------------------------------
#define ASTRIDE 72

__global__ void __launch_bounds__(128) attn_kernel()
{
    __shared__ __align__(16) __half sT[64*ASTRIDE];  // Q, then K
    __shared__ __align__(16) __half sV[64*ASTRIDE];

    const int tid  = threadIdx.x;
    const int lane = tid & 31;
    const int w    = tid >> 5;         // 0..3
    const int qb   = blockIdx.x;
    const int bh   = blockIdx.y;
    const int q0   = qb * 64;

    const uint32_t a0 = smem_to_u32(sT);
    const uint32_t av = smem_to_u32(sV);

    // ---- load Q tile (fp16 raw copy) ----
    {
        const uint4* qg = (const uint4*)(g_qh + ((size_t)bh*Tz + q0)*Dz);
        #pragma unroll
        for (int u = 0; u < 4; u++) {
            int idx4 = tid + 128*u;
            int r = idx4 >> 3, d8 = idx4 & 7;
            *(uint4*)&sT[r*ASTRIDE + d8*8] = qg[idx4];
        }
    }
    __syncthreads();

    // ---- hoist Q A-frags (4 k-steps x 4 regs) ----
    uint32_t qf[4][4];
    {
        const int rowA = 16*w + (lane & 7) + 8*((lane >> 3) & 1);
        const int colb = ((lane >> 4) & 1) * 16;
        #pragma unroll
        for (int j = 0; j < 4; j++)
            ldm4(qf[j], a0 + (uint32_t)(rowA*144 + j*32 + colb));
    }
    __syncthreads();   // Q smem now dead; K may overwrite

    float mr[2] = {-1e30f, -1e30f};
    float lr[2] = {0.f, 0.f};
    float O[8][4];
    #pragma unroll
    for (int aI = 0; aI < 8; aI++)
        #pragma unroll
        for (int e = 0; e < 4; e++) O[aI][e] = 0.f;

    const int r0loc = 16*w + (lane >> 2);   // block-local row for softmax/mask

    for (int kb = 0; kb <= qb; kb++) {
        // ---- load K and V tiles (fp16 raw copies) ----
        {
            const uint4* kg = (const uint4*)(g_kh + ((size_t)bh*Tz + kb*64)*Dz);
            const uint4* vg = (const uint4*)(g_vh + ((size_t)bh*Tz + kb*64)*Dz);
            #pragma unroll
            for (int u = 0; u < 4; u++) {
                int idx4 = tid + 128*u;
                int r = idx4 >> 3, d8 = idx4 & 7;
                *(uint4*)&sT[r*ASTRIDE + d8*8] = kg[idx4];
                *(uint4*)&sV[r*ASTRIDE + d8*8] = vg[idx4];
            }
        }
        __syncthreads();

        // ---- S = Q K^T (single fp16 pass) ----
        float S[8][4];
        #pragma unroll
        for (int aI = 0; aI < 8; aI++)
            #pragma unroll
            for (int e = 0; e < 4; e++) S[aI][e] = 0.f;

        const int rowB = (lane & 7) + 8*((lane >> 4) & 1);
        const int colbB = ((lane >> 3) & 1) * 16;
        #pragma unroll
        for (int j = 0; j < 4; j++) {
            #pragma unroll
            for (int p = 0; p < 4; p++) {
                uint32_t kf[4];
                ldm4(kf, a0 + (uint32_t)((16*p + rowB)*144 + j*32 + colbB));
                mma_f16(S[2*p],   qf[j], kf);
                mma_f16(S[2*p+1], qf[j], kf + 2);
            }
        }

        // ---- scale + causal mask (diagonal block only) ----
        const float sc = 0.125f;
        #pragma unroll
        for (int aI = 0; aI < 8; aI++) {
            int colb0 = 16*(aI >> 1) + 8*(aI & 1) + 2*(lane & 3);
            #pragma unroll
            for (int e = 0; e < 2; e++) {
                S[aI][e]   *= sc;
                S[aI][2+e] *= sc;
                if (kb == qb) {
                    if (colb0 + e > r0loc)     S[aI][e]   = -1e30f;
                    if (colb0 + e > r0loc + 8) S[aI][2+e] = -1e30f;
                }
            }
        }

        // ---- online softmax (rows r0loc and r0loc+8) ----
        float alpha[2];
        #pragma unroll
        for (int hrow = 0; hrow < 2; hrow++) {
            float mx = -1e30f;
            #pragma unroll
            for (int aI = 0; aI < 8; aI++)
                mx = fmaxf(mx, fmaxf(S[aI][2*hrow], S[aI][2*hrow+1]));
            mx = fmaxf(mx, __shfl_xor_sync(0xffffffffu, mx, 1));
            mx = fmaxf(mx, __shfl_xor_sync(0xffffffffu, mx, 2));
            float mn = fmaxf(mr[hrow], mx);
            alpha[hrow] = __expf(mr[hrow] - mn);
            mr[hrow] = mn;
            float rs = 0.f;
            #pragma unroll
            for (int aI = 0; aI < 8; aI++) {
                S[aI][2*hrow]   = __expf(S[aI][2*hrow]   - mn);
                S[aI][2*hrow+1] = __expf(S[aI][2*hrow+1] - mn);
                rs += S[aI][2*hrow] + S[aI][2*hrow+1];
            }
            rs += __shfl_xor_sync(0xffffffffu, rs, 1);
            rs += __shfl_xor_sync(0xffffffffu, rs, 2);
            lr[hrow] = lr[hrow] * alpha[hrow] + rs;
        }
        #pragma unroll
        for (int aI = 0; aI < 8; aI++) {
            O[aI][0] *= alpha[0]; O[aI][1] *= alpha[0];
            O[aI][2] *= alpha[1]; O[aI][3] *= alpha[1];
        }

        // ---- O += P V (fp16, P packed from S accums) ----
        #pragma unroll
        for (int j = 0; j < 4; j++) {
            uint32_t pa[4];
            __half2 t0 = __floats2half2_rn(S[2*j][0],   S[2*j][1]);
            __half2 t1 = __floats2half2_rn(S[2*j][2],   S[2*j][3]);
            __half2 t2 = __floats2half2_rn(S[2*j+1][0], S[2*j+1][1]);
            __half2 t3 = __floats2half2_rn(S[2*j+1][2], S[2*j+1][3]);
            pa[0] = *(uint32_t*)&t0; pa[1] = *(uint32_t*)&t1;
            pa[2] = *(uint32_t*)&t2; pa[3] = *(uint32_t*)&t3;
            const int rowV = 16*j + (lane & 7) + 8*((lane >> 3) & 1);
            #pragma unroll
            for (int q = 0; q < 4; q++) {
                uint32_t vb[4];
                ldm4t(vb, av + (uint32_t)(rowV*144 + (2*q + ((lane >> 4) & 1))*16));
                mma_f16(O[2*q],   pa, vb);
                mma_f16(O[2*q+1], pa, vb + 2);
            }
        }
        __syncthreads();   // protect K/V tiles before next iteration's overwrite
    }

    // ---- normalize + store fp16 to g_yh [m][h*64+d] ----
    const float inv0 = 1.0f / lr[0];
    const float inv1 = 1.0f / lr[1];
    const int b = bh >> 4;
    const int h = bh & 15;
    const int t0g = q0 + r0loc;
    #pragma unroll
    for (int aI = 0; aI < 8; aI++) {
        int d = 16*(aI >> 1) + 8*(aI & 1) + 2*(lane & 3);
        __half2 h0 = __floats2half2_rn(O[aI][0]*inv0, O[aI][1]*inv0);
        __half2 h1 = __floats2half2_rn(O[aI][2]*inv1, O[aI][3]*inv1);
        *(__half2*)&g_yh[((size_t)(b*Tz + t0g))*Cz + h*Dz + d]     = h0;
        *(__half2*)&g_yh[((size_t)(b*Tz + t0g + 8))*Cz + h*Dz + d] = h1;
    }
}

// ---------------------------------------------------------------------------
extern "C" void kernel_launch(void* const* d_in, const int* in_sizes, int n_in,
                              void* d_out, int out_size)
{
    const float* x     = (const float*)d_in[0];
    const float* Wqkv  = (const float*)d_in[1];
    const float* bqkv  = (const float*)d_in[2];
    const float* Wproj = (const float*)d_in[3];
    const float* bproj = (const float*)d_in[4];
    float* out = (float*)d_out;

    // 1) prep: x -> fp16 ; W^T -> fp16
    cvt_x_kernel<<<2048, 256>>>(x);
    transpose_cvt_kernel<<<dim3(3*Cz/32, Cz/32), dim3(32,8)>>>(Wqkv, 3*Cz, 0);
    transpose_cvt_kernel<<<dim3(Cz/32,   Cz/32), dim3(32,8)>>>(Wproj, Cz, 1);

    // 2) QKV GEMM (fp16 HMMA) -> scatter fp16 into g_qh/g_kh/g_vh
    mma_gemm_kernel<<<dim3(3*Cz/128, Mz/128), 256>>>(0, 3*Cz, bqkv, nullptr);

    // 3) causal flash attention (fp16 HMMA) -> g_yh
    attn_kernel<<<dim3(Tz/64, Bz*Hz), 128>>>();

    // 4) proj GEMM (fp16 HMMA) -> d_out
    mma_gemm_kernel<<<dim3(Cz/128, Mz/128), 256>>>(1, Cz, bproj, out);
}